// round 11
// baseline (speedup 1.0000x reference)
#include <cuda_runtime.h>
#include <cuda_bf16.h>

// Problem constants (fixed by the dataset)
#define BB 16
#define TT 512
#define DD 384
#define D8 (DD / 8)          // 48 float8 per row
#define MAXLEN 4096
#define NTHR 512
#define NWARP (NTHR / 32)    // 16
#define FPBLK 64             // frames per block
#define BPB (MAXLEN / FPBLK) // 64 blocks per batch -> grid = 1024
#define F8PT ((FPBLK * D8) / NTHR)   // 6 float8 per thread
#define BATCH 3              // 2 batches of 3 x 256-bit (MLP preserved in bytes)

// 256-bit global load (non-coherent) / streaming store — sm_100+/PTX 8.8
__device__ __forceinline__ void ldg256(const float* p, float* v) {
    asm volatile(
        "ld.global.nc.v8.f32 {%0,%1,%2,%3,%4,%5,%6,%7}, [%8];"
        : "=f"(v[0]), "=f"(v[1]), "=f"(v[2]), "=f"(v[3]),
          "=f"(v[4]), "=f"(v[5]), "=f"(v[6]), "=f"(v[7])
        : "l"(p));
}
__device__ __forceinline__ void stg256_cs(float* p, const float* v) {
    asm volatile(
        "st.global.cs.v8.f32 [%0], {%1,%2,%3,%4,%5,%6,%7,%8};"
        :: "l"(p),
           "f"(v[0]), "f"(v[1]), "f"(v[2]), "f"(v[3]),
           "f"(v[4]), "f"(v[5]), "f"(v[6]), "f"(v[7])
        : "memory");
}

// ---------------------------------------------------------------------------
// Fused kernel (R10 structure, 128-bit -> 256-bit memory ops):
//  - warp-shuffle inclusive scan of durations (proven)
//  - scatter inversion (proven): token t owns [cum[t-1], min(cum[t],lim))
//  - gather: 3 independent LDG.256 issued back-to-back, then 3 STG.256 (.cs)
// blockIdx.x = b * BPB + blk; block covers frames [blk*FPBLK, blk*FPBLK+FPBLK)
// ---------------------------------------------------------------------------
__global__ void __launch_bounds__(NTHR)
lr_fused(const float* __restrict__ x, const int* __restrict__ dur,
         float* __restrict__ out, int mode) {
    __shared__ int wsum[NWARP];
    __shared__ int fidx[FPBLK];   // frame -> token index for this window, -1 = zero
    __shared__ int s_mel;

    const int b    = blockIdx.x / BPB;
    const int blk  = blockIdx.x - b * BPB;
    const int t    = threadIdx.x;
    const int lane = t & 31;
    const int w    = t >> 5;

    // ---- inclusive scan of durations: warp shuffle + warp-total fixup ----
    const int v = __ldg(&dur[b * TT + t]);
    int sc = v;
    #pragma unroll
    for (int o = 1; o < 32; o <<= 1) {
        int n = __shfl_up_sync(0xffffffffu, sc, o);
        if (lane >= o) sc += n;
    }
    if (lane == 31) wsum[w] = sc;
    if (t < FPBLK) fidx[t] = -1;
    __syncthreads();
    if (w == 0 && lane < NWARP) {
        int ws = wsum[lane];
        #pragma unroll
        for (int o = 1; o < NWARP; o <<= 1) {
            int n = __shfl_up_sync(0x0000ffffu, ws, o);
            if (lane >= o) ws += n;
        }
        wsum[lane] = ws;
        if (lane == NWARP - 1) s_mel = ws;   // total = mel_len
    }
    __syncthreads();

    const int end   = sc + (w ? wsum[w - 1] : 0);   // inclusive cum[t]
    const int start = end - v;                       // cum[t-1]
    const int mel   = s_mel;
    const int lim   = mel < MAXLEN ? mel : MAXLEN;
    const int f0    = blk * FPBLK;

    // ---- scatter inversion into this block's window (proven semantics) ----
    {
        const int e2 = end < lim ? end : lim;
        int a  = start > f0 ? start : f0;
        int bd = e2 < (f0 + FPBLK) ? e2 : (f0 + FPBLK);
        for (int f = a; f < bd; ++f) fidx[f - f0] = t;        // durations < 8
    }

    // mel_len tail (output 1), written once per batch by block 0
    if (blk == 0 && t == 0 && mode) {
        const long long base = (long long)BB * MAXLEN * DD;
        if (mode == 1)      out[base + b] = (float)mel;
        else                ((long long*)(out + base))[b] = (long long)mel;
    }
    __syncthreads();

    // ---- gather + streaming store: 2 batches of 3 LDG.256 then 3 STG.256 ----
    const float* xb = x + (size_t)b * TT * DD;
    float* ob = out + ((size_t)b * MAXLEN + f0) * DD;
    #pragma unroll
    for (int k0 = 0; k0 < F8PT; k0 += BATCH) {
        float val[BATCH][8];
        int   g[BATCH];
        #pragma unroll
        for (int j = 0; j < BATCH; ++j) {
            g[j] = t + (k0 + j) * NTHR;          // float8 chunk index, < 3072
            const int fl = g[j] / D8;            // frame within window
            const int d8 = g[j] - fl * D8;       // float8 offset within row
            const int id = fidx[fl];
            if (id >= 0) {
                ldg256(&xb[(id * D8 + d8) * 8], val[j]);
            } else {
                #pragma unroll
                for (int e = 0; e < 8; ++e) val[j][e] = 0.f;
            }
        }
        #pragma unroll
        for (int j = 0; j < BATCH; ++j) {
            stg256_cs(&ob[g[j] * 8], val[j]);
        }
    }
}

extern "C" void kernel_launch(void* const* d_in, const int* in_sizes, int n_in,
                              void* d_out, int out_size) {
    const float* x   = (const float*)d_in[0];
    const int*   dur = (const int*)d_in[1];   // int32 (JAX x64 disabled)

    const long long base = (long long)BB * MAXLEN * DD;   // 25,165,824 f32
    int mode = 0;
    if ((long long)out_size == base + BB)            mode = 1;  // mel as f32
    else if ((long long)out_size == base + 2 * BB)   mode = 2;  // mel as i64

    lr_fused<<<BB * BPB, NTHR>>>(x, dur, (float*)d_out, mode);
}

// round 12
// speedup vs baseline: 1.3012x; 1.3012x over previous
#include <cuda_runtime.h>
#include <cuda_bf16.h>

// Problem constants (fixed by the dataset)
#define BB 16
#define TT 512
#define DD 384
#define D4 (DD / 4)          // 96 float4 per row
#define MAXLEN 4096
#define NTHR 512
#define NWARP (NTHR / 32)    // 16
#define FPBLK 64             // frames per block
#define BPB (MAXLEN / FPBLK) // 64 blocks per batch -> grid = 1024
#define FPW (FPBLK / NWARP)  // 4 frames per warp
#define ITER (D4 / 32)       // 3 float4 per lane per frame

// ---------------------------------------------------------------------------
// Fused kernel (R10 logic; gather remapped warp-per-frame):
//  - warp-shuffle inclusive scan of durations (proven)
//  - scatter inversion (proven): token t owns [cum[t-1], min(cum[t],lim))
//  - gather: warp w owns frames [w*4, w*4+4); lane l covers float4 l+32*i.
//    No div/mod, fidx read once per frame (uniform broadcast), 6 LDG.128 in
//    flight (2 frames x 3), then 6 STG.128 (.cs). Fully coalesced both ways.
// ---------------------------------------------------------------------------
__global__ void __launch_bounds__(NTHR)
lr_fused(const float4* __restrict__ x, const int* __restrict__ dur,
         float* __restrict__ out, int mode) {
    __shared__ int wsum[NWARP];
    __shared__ int fidx[FPBLK];   // frame -> token index for this window, -1 = zero
    __shared__ int s_mel;

    const int b    = blockIdx.x / BPB;
    const int blk  = blockIdx.x - b * BPB;
    const int t    = threadIdx.x;
    const int lane = t & 31;
    const int w    = t >> 5;

    // ---- inclusive scan of durations: warp shuffle + warp-total fixup ----
    const int v = __ldg(&dur[b * TT + t]);
    int sc = v;
    #pragma unroll
    for (int o = 1; o < 32; o <<= 1) {
        int n = __shfl_up_sync(0xffffffffu, sc, o);
        if (lane >= o) sc += n;
    }
    if (lane == 31) wsum[w] = sc;
    if (t < FPBLK) fidx[t] = -1;
    __syncthreads();
    if (w == 0 && lane < NWARP) {
        int ws = wsum[lane];
        #pragma unroll
        for (int o = 1; o < NWARP; o <<= 1) {
            int n = __shfl_up_sync(0x0000ffffu, ws, o);
            if (lane >= o) ws += n;
        }
        wsum[lane] = ws;
        if (lane == NWARP - 1) s_mel = ws;   // total = mel_len
    }
    __syncthreads();

    const int end   = sc + (w ? wsum[w - 1] : 0);   // inclusive cum[t]
    const int start = end - v;                       // cum[t-1]
    const int mel   = s_mel;
    const int lim   = mel < MAXLEN ? mel : MAXLEN;
    const int f0    = blk * FPBLK;

    // ---- scatter inversion into this block's window (proven semantics) ----
    {
        const int e2 = end < lim ? end : lim;
        int a  = start > f0 ? start : f0;
        int bd = e2 < (f0 + FPBLK) ? e2 : (f0 + FPBLK);
        for (int f = a; f < bd; ++f) fidx[f - f0] = t;        // durations < 8
    }

    // mel_len tail (output 1), written once per batch by block 0
    if (blk == 0 && t == 0 && mode) {
        const long long base = (long long)BB * MAXLEN * DD;
        if (mode == 1)      out[base + b] = (float)mel;
        else                ((long long*)(out + base))[b] = (long long)mel;
    }
    __syncthreads();

    // ---- gather + streaming store: warp-per-frame, 2 frames in flight ----
    const float4* xb = x + (size_t)b * TT * D4;
    float4* ob = (float4*)((float*)out) + ((size_t)b * MAXLEN + f0) * D4;
    const int fr0 = w * FPW;                 // this warp's first frame

    #pragma unroll
    for (int p = 0; p < FPW; p += 2) {       // 2 frames per batch
        const int fA = fr0 + p;
        const int fB = fr0 + p + 1;
        const int idA = fidx[fA];            // uniform per warp (broadcast)
        const int idB = fidx[fB];
        float4 valA[ITER], valB[ITER];
        #pragma unroll
        for (int i = 0; i < ITER; ++i) {
            valA[i] = make_float4(0.f, 0.f, 0.f, 0.f);
            if (idA >= 0) valA[i] = __ldg(&xb[idA * D4 + lane + 32 * i]);
        }
        #pragma unroll
        for (int i = 0; i < ITER; ++i) {
            valB[i] = make_float4(0.f, 0.f, 0.f, 0.f);
            if (idB >= 0) valB[i] = __ldg(&xb[idB * D4 + lane + 32 * i]);
        }
        #pragma unroll
        for (int i = 0; i < ITER; ++i)
            __stcs(&ob[fA * D4 + lane + 32 * i], valA[i]);
        #pragma unroll
        for (int i = 0; i < ITER; ++i)
            __stcs(&ob[fB * D4 + lane + 32 * i], valB[i]);
    }
}

extern "C" void kernel_launch(void* const* d_in, const int* in_sizes, int n_in,
                              void* d_out, int out_size) {
    const float* x   = (const float*)d_in[0];
    const int*   dur = (const int*)d_in[1];   // int32 (JAX x64 disabled)

    const long long base = (long long)BB * MAXLEN * DD;   // 25,165,824 f32
    int mode = 0;
    if ((long long)out_size == base + BB)            mode = 1;  // mel as f32
    else if ((long long)out_size == base + 2 * BB)   mode = 2;  // mel as i64

    lr_fused<<<BB * BPB, NTHR>>>((const float4*)x, dur, (float*)d_out, mode);
}